// round 1
// baseline (speedup 1.0000x reference)
#include <cuda_runtime.h>

// DILATE loss: 0.5 * soft-DTW(D) mean  +  0.5 * sum(E * (i-j)^2) / (N^2 B^2)
// D[b,i,j] = max(||t_i||^2 + ||o_j||^2 - 2 t_i.o_j, 0),  gamma = 1, BIG = 1e8.
//
// One CTA per batch element. Anti-diagonal wavefront forward (R) + backward (E).
// R stored diagonal-major in a __device__ global for coalesced store/load.

#define NB   256
#define NN   336
#define NV   7
#define ND   (2*NN + 1)   // diag indices 0..672
#define DS   352          // padded per-diagonal stride (multiple of 32)
#define TPB  352
#define BIGV 1.0e8f
#define BUFW 344          // rolling diag buffer width (>= NN+2)

__device__ float  g_R[(size_t)NB * ND * DS];
__device__ double g_shape;
__device__ double g_temporal;

__global__ void init_kernel() {
    g_shape = 0.0;
    g_temporal = 0.0;
}

__global__ __launch_bounds__(TPB, 2)
void dilate_kernel(const float* __restrict__ outputs,
                   const float* __restrict__ targets) {
    const int b   = blockIdx.x;
    const int tid = threadIdx.x;
    const int i   = tid + 1;               // DP row handled by this thread (1-based)
    const bool has_row = (tid < NN);

    __shared__ float o_s[8 * NN];          // [v][j] for v<7, [7][j] = ||o_j||^2
    __shared__ float dbuf[6][BUFW];        // rolling anti-diagonal buffers
    __shared__ float warpsum[TPB / 32];

    const float* ob = outputs + (size_t)b * NN * NV;
    const float* tb = targets + (size_t)b * NN * NV;

    // --- load outputs transposed into smem ---
    for (int k = tid; k < NN * NV; k += TPB) {
        int j = k / NV, v = k - j * NV;
        o_s[v * NN + j] = ob[k];
    }
    __syncthreads();
    // norms of output rows
    for (int j = tid; j < NN; j += TPB) {
        float s = 0.f;
#pragma unroll
        for (int v = 0; v < NV; v++) { float x = o_s[v * NN + j]; s = fmaf(x, x, s); }
        o_s[7 * NN + j] = s;
    }
    // target row into registers
    float t[NV];
    float tn = 0.f;
    if (has_row) {
#pragma unroll
        for (int v = 0; v < NV; v++) { t[v] = tb[tid * NV + v]; tn = fmaf(t[v], t[v], tn); }
    }
    // init forward R-diagonal buffers (3 buffers) to BIG
    for (int k = tid; k < 3 * BUFW; k += TPB) (&dbuf[0][0])[k] = BIGV;
    __syncthreads();
    if (tid == 0) dbuf[0][0] = 0.f;        // R[0,0] = 0 (diag 0)
    __syncthreads();

    float* gR = g_R + (size_t)b * (ND * DS);

    // ================= forward =================
    for (int d = 2; d <= 2 * NN; d++) {
        float* cur = dbuf[d % 3];
        float* p1  = dbuf[(d + 2) % 3];    // diag d-1
        float* p2  = dbuf[(d + 1) % 3];    // diag d-2
        int j = d - i;
        bool act = has_row && (j >= 1) && (j <= NN);
        if (act) {
            float dot = 0.f;
#pragma unroll
            for (int v = 0; v < NV; v++) dot = fmaf(t[v], o_s[v * NN + (j - 1)], dot);
            float Dij = fmaxf(tn + o_s[7 * NN + (j - 1)] - 2.f * dot, 0.f);
            float rd = p2[i - 1];          // R[i-1,j-1]
            float ru = p1[i - 1];          // R[i-1,j]
            float rl = p1[i];              // R[i,j-1]
            float m  = fminf(rd, fminf(ru, rl));
            float z  = __expf(m - rd) + __expf(m - ru) + __expf(m - rl);
            float Rv = Dij + m - __logf(z);
            cur[i] = Rv;
            gR[(size_t)d * DS + i] = Rv;
        }
        if (tid == 0) cur[0] = BIGV;       // R[0,d] boundary
        __syncthreads();
    }

    // ================= backward =================
    // reuse dbuf: E in dbuf[0..2], s = R - D in dbuf[3..5]; zero-init all.
    for (int k = tid; k < 6 * BUFW; k += TPB) (&dbuf[0][0])[k] = 0.f;
    __syncthreads();

    float acc = 0.f;
    for (int d = 2 * NN; d >= 2; d--) {
        float* Ec = dbuf[d % 3];
        float* E1 = dbuf[(d + 1) % 3];     // diag d+1
        float* E2 = dbuf[(d + 2) % 3];     // diag d+2
        float* sc = dbuf[3 + d % 3];
        float* s1 = dbuf[3 + (d + 1) % 3];
        float* s2 = dbuf[3 + (d + 2) % 3];
        int j = d - i;
        bool act = has_row && (j >= 1) && (j <= NN);
        if (act) {
            float Rij = gR[(size_t)d * DS + i];
            float dot = 0.f;
#pragma unroll
            for (int v = 0; v < NV; v++) dot = fmaf(t[v], o_s[v * NN + (j - 1)], dot);
            float Dij = fmaxf(tn + o_s[7 * NN + (j - 1)] - 2.f * dot, 0.f);
            float Ev;
            if (d == 2 * NN) {
                Ev = 1.0f;                 // seed at (N,N)
                atomicAdd(&g_shape, (double)Rij);
            } else {
                Ev = E1[i + 1] * __expf(s1[i + 1] - Rij)   // up-successor (i+1, j)
                   + E1[i]     * __expf(s1[i]     - Rij)   // left-successor (i, j+1)
                   + E2[i + 1] * __expf(s2[i + 1] - Rij);  // diag-successor (i+1, j+1)
            }
            Ec[i] = Ev;
            sc[i] = Rij - Dij;
            float diff = (float)(2 * i - d);               // i - j
            acc = fmaf(Ev, diff * diff, acc);
        }
        __syncthreads();
    }

    // ------- block reduction of temporal accumulator -------
#pragma unroll
    for (int off = 16; off; off >>= 1) acc += __shfl_down_sync(0xffffffffu, acc, off);
    if ((tid & 31) == 0) warpsum[tid >> 5] = acc;
    __syncthreads();
    if (tid == 0) {
        float s = 0.f;
#pragma unroll
        for (int w = 0; w < TPB / 32; w++) s += warpsum[w];
        atomicAdd(&g_temporal, (double)s);
    }
}

__global__ void finalize_kernel(float* out) {
    double shape    = g_shape / (double)NB;
    double temporal = g_temporal / ((double)NN * NN * NB * NB);
    out[0] = (float)(0.5 * shape + 0.5 * temporal);
}

extern "C" void kernel_launch(void* const* d_in, const int* in_sizes, int n_in,
                              void* d_out, int out_size) {
    const float* outputs = (const float*)d_in[0];
    const float* targets = (const float*)d_in[1];
    init_kernel<<<1, 1>>>();
    dilate_kernel<<<NB, TPB>>>(outputs, targets);
    finalize_kernel<<<1, 1>>>((float*)d_out);
}

// round 2
// speedup vs baseline: 1.0973x; 1.0973x over previous
#include <cuda_runtime.h>

// DILATE loss, fused single kernel.
// loss = 0.5 * mean_b R_b[N,N]  +  0.5 * sum(E * (i-j)^2) / (N^2 * B^2)
// Soft-DTW forward (R) + backward (E) as anti-diagonal wavefronts, one CTA per batch.
// All math in base-2 (R' = R * log2(e)) so exps/logs are raw ex2/lg2.approx MUFU ops.
// Forward softmin uses min/median/max network: one of the 3 exps is exp(0)=1.

#define NB    256
#define NN    336
#define NV    7
#define ND    (2*NN + 1)
#define DS    352            // padded per-diagonal stride (coalesced)
#define TPB   352
#define BUFW  344
#define LOG2E 1.4426950408889634f
#define LN2   0.6931471805599453f
#define BIG2  (1.0e8f * LOG2E)

__device__ float    g_R[(size_t)NB * ND * DS];
__device__ double   g_shape_acc;     // zero-init at load; last CTA resets each call
__device__ double   g_temp_acc;
__device__ unsigned g_done;

__device__ __forceinline__ float ex2f(float x) {
    float r; asm("ex2.approx.f32 %0, %1;" : "=f"(r) : "f"(x)); return r;
}
__device__ __forceinline__ float lg2f(float x) {
    float r; asm("lg2.approx.f32 %0, %1;" : "=f"(r) : "f"(x)); return r;
}

__global__ __launch_bounds__(TPB, 2)
void dilate_kernel(const float* __restrict__ outputs,
                   const float* __restrict__ targets,
                   float* __restrict__ out) {
    const int b   = blockIdx.x;
    const int tid = threadIdx.x;
    const int i   = tid + 1;                 // DP row (1-based)
    const bool has_row = (tid < NN);

    __shared__ float o_s[8 * NN];            // [v][j] v<7; [7][j] = ||o_j||^2 (base-e units)
    __shared__ float dbuf[6][BUFW];          // rolling anti-diagonal rings
    __shared__ float warpsum[TPB / 32];
    __shared__ float shape_s;

    const float* ob = outputs + (size_t)b * NN * NV;
    const float* tb = targets + (size_t)b * NN * NV;

    // load outputs transposed
    for (int k = tid; k < NN * NV; k += TPB) {
        int j = k / NV, v = k - j * NV;
        o_s[v * NN + j] = ob[k];
    }
    __syncthreads();
    for (int j = tid; j < NN; j += TPB) {
        float s = 0.f;
#pragma unroll
        for (int v = 0; v < NV; v++) { float x = o_s[v * NN + j]; s = fmaf(x, x, s); }
        o_s[7 * NN + j] = s;
    }
    float t[NV], tn = 0.f;
    if (has_row) {
#pragma unroll
        for (int v = 0; v < NV; v++) { t[v] = tb[tid * NV + v]; tn = fmaf(t[v], t[v], tn); }
    }
    // init forward rings to BIG; R[0,0]=0 lives in ring slot 0 of buf0
    for (int k = tid; k < 3 * BUFW; k += TPB) (&dbuf[0][0])[k] = BIG2;
    __syncthreads();
    if (tid == 0) dbuf[0][0] = 0.f;
    __syncthreads();

    float* gR = g_R + (size_t)b * (ND * DS) + i;

    // ================= forward =================
    for (int d = 2; d <= 2 * NN; d++) {
        float* cur = dbuf[d % 3];
        float* p1  = dbuf[(d + 2) % 3];      // diag d-1
        float* p2  = dbuf[(d + 1) % 3];      // diag d-2
        int j = d - i;
        if (has_row && j >= 1 && j <= NN) {
            int jm1 = j - 1;
            float dot = 0.f;
#pragma unroll
            for (int v = 0; v < NV; v++) dot = fmaf(t[v], o_s[v * NN + jm1], dot);
            float D2 = fmaxf(fmaf(-2.f, dot, tn + o_s[7 * NN + jm1]), 0.f) * LOG2E;
            float rd = p2[i - 1], ru = p1[i - 1], rl = p1[i];
            float lo = fminf(rd, ru), hi = fmaxf(rd, ru);
            float m  = fminf(lo, rl);
            float md = fmaxf(lo, fminf(hi, rl));
            float Mx = fmaxf(hi, rl);
            float z  = 1.f + ex2f(m - md) + ex2f(m - Mx);
            float Rv = D2 + m - lg2f(z);
            cur[i] = Rv;
            gR[(size_t)d * DS] = Rv;
        }
        if (tid == NN) cur[0] = BIG2;        // boundary R[0,d] for future diagonals
        __syncthreads();
    }

    // ================= backward =================
    // rings: E in dbuf[0..2], s' = R' - D' in dbuf[3..5]; zero-init
    for (int k = tid; k < 6 * BUFW; k += TPB) (&dbuf[0][0])[k] = 0.f;
    __syncthreads();

    float acc = 0.f;
    float diff_f = (float)(2 * i - 2 * NN);  // i - j, incremented as d decreases
    for (int d = 2 * NN; d >= 2; d--) {
        float* Ec = dbuf[d % 3];
        float* E1 = dbuf[(d + 1) % 3];
        float* E2 = dbuf[(d + 2) % 3];
        float* sc = dbuf[3 + d % 3];
        float* s1 = dbuf[3 + (d + 1) % 3];
        float* s2 = dbuf[3 + (d + 2) % 3];
        int j = d - i;
        if (has_row && j >= 1 && j <= NN) {
            float Rij = gR[(size_t)d * DS];
            int jm1 = j - 1;
            float dot = 0.f;
#pragma unroll
            for (int v = 0; v < NV; v++) dot = fmaf(t[v], o_s[v * NN + jm1], dot);
            float D2 = fmaxf(fmaf(-2.f, dot, tn + o_s[7 * NN + jm1]), 0.f) * LOG2E;
            float Ev;
            if (d == 2 * NN) {
                Ev = 1.0f;
                shape_s = Rij * LN2;         // only thread i==NN active here
            } else {
                Ev = E1[i + 1] * ex2f(s1[i + 1] - Rij)
                   + E1[i]     * ex2f(s1[i]     - Rij)
                   + E2[i + 1] * ex2f(s2[i + 1] - Rij);
            }
            Ec[i] = Ev;
            sc[i] = Rij - D2;
            acc = fmaf(Ev, diff_f * diff_f, acc);
        }
        diff_f += 1.f;
        __syncthreads();
    }

    // block reduction of temporal accumulator
#pragma unroll
    for (int off = 16; off; off >>= 1) acc += __shfl_down_sync(0xffffffffu, acc, off);
    if ((tid & 31) == 0) warpsum[tid >> 5] = acc;
    __syncthreads();
    if (tid == 0) {
        float s = 0.f;
#pragma unroll
        for (int w = 0; w < TPB / 32; w++) s += warpsum[w];
        atomicAdd(&g_temp_acc, (double)s);
        atomicAdd(&g_shape_acc, (double)shape_s);
        __threadfence();
        unsigned old = atomicAdd(&g_done, 1u);
        if (old == NB - 1) {                 // last CTA finalizes and resets
            __threadfence();
            double shape    = g_shape_acc / (double)NB;
            double temporal = g_temp_acc / ((double)NN * NN * NB * NB);
            out[0] = (float)(0.5 * shape + 0.5 * temporal);
            g_shape_acc = 0.0;
            g_temp_acc  = 0.0;
            __threadfence();
            g_done = 0u;
        }
    }
}

extern "C" void kernel_launch(void* const* d_in, const int* in_sizes, int n_in,
                              void* d_out, int out_size) {
    const float* outputs = (const float*)d_in[0];
    const float* targets = (const float*)d_in[1];
    dilate_kernel<<<NB, TPB>>>(outputs, targets, (float*)d_out);
}

// round 3
// speedup vs baseline: 1.8297x; 1.6675x over previous
#include <cuda_runtime.h>

// DILATE loss, shuffle-pipelined band-wavefront soft-DTW (fwd + bwd), one CTA/batch.
// Warp w owns rows [32w+1, 32w+32]; lane l column-staggered; intra-warp deps via shfl,
// cross-band boundary rows via smem with 64-column warp skew; barrier once per 32 steps.
// Base-2 math throughout (R' = R*log2e). R stored diagonal-major in gmem (coalesced),
// re-read in backward through a 16-deep register prefetch ring.

#define NB    256
#define NN    336
#define NV    7
#define ND    673            // diagonals 0..672
#define DS    352            // per-diagonal stride
#define TPB   352
#define NW    11
#define BNDW  344
#define LOG2E 1.4426950408889634f
#define LN2   0.6931471805599453f
#define BIG2  1.442695e8f    // 1e8 * log2(e)
#define NEGS  -1.0e30f
#define PF    16
#define FULLM 0xffffffffu

__device__ float    g_R[(size_t)NB * ND * DS];
__device__ double   g_shape_acc;
__device__ double   g_temp_acc;
__device__ unsigned g_done;

static __device__ __forceinline__ float ex2f(float x) {
    float r; asm("ex2.approx.f32 %0, %1;" : "=f"(r) : "f"(x)); return r;
}
static __device__ __forceinline__ float lg2f(float x) {
    float r; asm("lg2.approx.f32 %0, %1;" : "=f"(r) : "f"(x)); return r;
}

__global__ __launch_bounds__(TPB, 2)
void dilate_kernel(const float* __restrict__ outputs,
                   const float* __restrict__ targets,
                   float* __restrict__ out) {
    const int b   = blockIdx.x;
    const int tid = threadIdx.x;
    const int w   = tid >> 5;
    const int l   = tid & 31;
    const int i   = 32 * w + l + 1;          // DP row (1-based)
    const bool row_ok = (i <= NN);

    __shared__ float o_s[8 * NN];            // [v][j], v<7; [7][j]=||o_j||^2
    __shared__ float bndA[NW][BNDW];         // fwd: R[32w][j] ; bwd: E[32w+33][j]
    __shared__ float bndB[NW][BNDW];         // bwd: s[32w+33][j]
    __shared__ float warpsum[NW];
    __shared__ float shape_s;

    const float* ob = outputs + (size_t)b * NN * NV;
    const float* tb = targets + (size_t)b * NN * NV;

    for (int k = tid; k < NN * NV; k += TPB) {
        int j = k / NV, v = k - j * NV;
        o_s[v * NN + j] = ob[k];
    }
    __syncthreads();
    for (int j = tid; j < NN; j += TPB) {
        float s = 0.f;
#pragma unroll
        for (int v = 0; v < NV; v++) { float x = o_s[v * NN + j]; s = fmaf(x, x, s); }
        o_s[7 * NN + j] = s;
    }
    float t[NV], tn = 0.f;
    if (row_ok) {
#pragma unroll
        for (int v = 0; v < NV; v++) { t[v] = tb[(i - 1) * NV + v]; tn = fmaf(t[v], t[v], tn); }
    }
    // forward boundary prefill: row 0 (all BIG except R[0][0]=0), column 0 for each band
    for (int k = tid; k < BNDW; k += TPB) bndA[0][k] = (k == 0) ? 0.f : BIG2;
    if (tid > 0 && tid < NW) bndA[tid][0] = BIG2;
    if (tid == 0) shape_s = 0.f;
    __syncthreads();

    float* gRb = g_R + (size_t)b * ND * DS;

    // ================= forward =================
    {
        float Rprev = BIG2, upc = BIG2, upp = BIG2, prevB = 0.f;
        const int off = 64 * w;
        const int pstart = off >> 5, pend = (off + 366) >> 5;
        for (int p = 0; p < 31; p++) {
            if (p >= pstart && p <= pend) {
                if (p == pstart && l == 0) prevB = bndA[w][0];
                int s = p << 5;
#pragma unroll 8
                for (int k = 0; k < 32; k++, s++) {
                    int j = s - off - l + 1;
                    bool act = row_ok && (j >= 1) && (j <= NN);
                    int jm = min(max(j - 1, 0), NN - 1);
                    float dot = 0.f;
#pragma unroll
                    for (int v = 0; v < NV; v++) dot = fmaf(t[v], o_s[v * NN + jm], dot);
                    float D2 = fmaxf(fmaf(-2.f, dot, tn + o_s[7 * NN + jm]), 0.f) * LOG2E;
                    float ru = upc, rd = upp, curB = 0.f;
                    if (l == 0) {
                        int jc = min(max(j, 0), BNDW - 1);
                        curB = bndA[w][jc];
                        ru = curB; rd = prevB;
                    }
                    float rl = Rprev;
                    float lo = fminf(rd, ru), hi = fmaxf(rd, ru);
                    float m  = fminf(lo, rl);
                    float md = fmaxf(lo, fminf(hi, rl));
                    float Mx = fmaxf(hi, rl);
                    float z  = 1.f + ex2f(m - md) + ex2f(m - Mx);
                    float Rn = D2 + m - lg2f(z);
                    Rn = act ? Rn : BIG2;
                    if (act) {
                        gRb[(size_t)(s - 32 * w + 2) * DS + i] = Rn;  // diag d = i+j
                        if (l == 31 && w < NW - 1) bndA[w + 1][j] = Rn;
                    }
                    float sh = __shfl_up_sync(FULLM, Rn, 1);
                    upp = upc; upc = sh;
                    if (l == 0) prevB = curB;
                    Rprev = Rn;
                }
            }
            __syncthreads();
        }
    }

    // re-init boundary arrays for backward (E=0, s=NEG beyond edges)
    for (int k = tid; k < NW * BNDW; k += TPB) {
        (&bndA[0][0])[k] = 0.f;
        (&bndB[0][0])[k] = NEGS;
    }
    __syncthreads();

    // ================= backward =================
    float acc = 0.f;
    {
        float Eprev = 0.f, Sprev = NEGS;     // (i, j+1)
        float Edn1  = 0.f, Sdn1  = NEGS;     // (i+1, j)
        float Edn2  = 0.f, Sdn2  = NEGS;     // (i+1, j+1)
        const int off = 64 * (10 - w);
        const int pstart = off >> 5, pend = (off + 366) >> 5;
        const int irow = min(i, DS - 1);
        float rring[PF];
        for (int p = 0; p < 32; p++) {
            if (p >= pstart && p <= pend) {
                int s0 = p << 5;
                if (p == pstart) {
#pragma unroll
                    for (int q = 0; q < PF; q++) {
                        int d = 1008 - 32 * w - (s0 + q);
                        d = min(max(d, 0), ND - 1);
                        rring[q] = gRb[(size_t)d * DS + irow];
                    }
                }
                int s = s0;
#pragma unroll 2
                for (int kb = 0; kb < 2; kb++) {
#pragma unroll
                    for (int kk = 0; kk < 16; kk++, s++) {
                        int j = 367 + off - s - l;
                        bool act = row_ok && (j >= 1) && (j <= NN);
                        float Rij = rring[kk];
                        {   // prefetch for step s+PF
                            int dpf = 1008 - 32 * w - (s + PF);
                            dpf = min(max(dpf, 0), ND - 1);
                            rring[kk] = gRb[(size_t)dpf * DS + irow];
                        }
                        if (l == 31) {       // cross-band successors from smem
                            int jc = min(max(j, 0), BNDW - 1);
                            Edn1 = bndA[w][jc];
                            Sdn1 = bndB[w][jc];
                        }
                        int jm = min(max(j - 1, 0), NN - 1);
                        float dot = 0.f;
#pragma unroll
                        for (int v = 0; v < NV; v++) dot = fmaf(t[v], o_s[v * NN + jm], dot);
                        float D2 = fmaxf(fmaf(-2.f, dot, tn + o_s[7 * NN + jm]), 0.f) * LOG2E;
                        float w1 = ex2f(Sdn1 - Rij);
                        float w2 = ex2f(Sprev - Rij);
                        float w3 = ex2f(Sdn2 - Rij);
                        float En = Edn1 * w1 + Eprev * w2 + Edn2 * w3;
                        if (i == NN && j == NN) { En = 1.f; shape_s = Rij * LN2; }
                        float Sn = Rij - D2;
                        En = act ? En : 0.f;
                        Sn = act ? Sn : NEGS;
                        if (act) {
                            float df = (float)(i - j);
                            acc = fmaf(En, df * df, acc);
                            if (l == 0 && w > 0) { bndA[w - 1][j] = En; bndB[w - 1][j] = Sn; }
                        }
                        float Es = __shfl_down_sync(FULLM, En, 1);
                        float Ss = __shfl_down_sync(FULLM, Sn, 1);
                        Edn2 = Edn1; Sdn2 = Sdn1;
                        Edn1 = Es;   Sdn1 = Ss;
                        Eprev = En;  Sprev = Sn;
                    }
                }
            }
            __syncthreads();
        }
    }

    // ------- reduce temporal accumulator, finalize in last CTA -------
#pragma unroll
    for (int o2 = 16; o2; o2 >>= 1) acc += __shfl_down_sync(FULLM, acc, o2);
    if (l == 0) warpsum[w] = acc;
    __syncthreads();
    if (tid == 0) {
        float sum = 0.f;
#pragma unroll
        for (int q = 0; q < NW; q++) sum += warpsum[q];
        atomicAdd(&g_temp_acc, (double)sum);
        atomicAdd(&g_shape_acc, (double)shape_s);
        __threadfence();
        unsigned old = atomicAdd(&g_done, 1u);
        if (old == NB - 1) {
            __threadfence();
            double shape    = g_shape_acc / (double)NB;
            double temporal = g_temp_acc / ((double)NN * NN * NB * NB);
            out[0] = (float)(0.5 * shape + 0.5 * temporal);
            g_shape_acc = 0.0;
            g_temp_acc  = 0.0;
            __threadfence();
            g_done = 0u;
        }
    }
}

extern "C" void kernel_launch(void* const* d_in, const int* in_sizes, int n_in,
                              void* d_out, int out_size) {
    const float* outputs = (const float*)d_in[0];
    const float* targets = (const float*)d_in[1];
    dilate_kernel<<<NB, TPB>>>(outputs, targets, (float*)d_out);
}

// round 4
// speedup vs baseline: 1.8301x; 1.0002x over previous
#include <cuda_runtime.h>

// DILATE loss, shuffle-pipelined band-wavefront soft-DTW (fwd + bwd), one CTA/batch.
// Warp w owns rows [32w+1, 32w+32]; lane l column-staggered; intra-warp deps via shfl,
// cross-band boundary rows via smem with 64-column warp skew; barrier once per 32 steps.
// Base-2 math throughout (R' = R*log2e). R stored diagonal-major in gmem (coalesced),
// re-read in backward through a 16-deep register prefetch ring.

#define NB    256
#define NN    336
#define NV    7
#define ND    673            // diagonals 0..672
#define DS    352            // per-diagonal stride
#define TPB   352
#define NW    11
#define BNDW  344
#define LOG2E 1.4426950408889634f
#define LN2   0.6931471805599453f
#define BIG2  1.442695e8f    // 1e8 * log2(e)
#define NEGS  -1.0e30f
#define PF    16
#define FULLM 0xffffffffu

__device__ float    g_R[(size_t)NB * ND * DS];
__device__ double   g_shape_acc;
__device__ double   g_temp_acc;
__device__ unsigned g_done;

static __device__ __forceinline__ float ex2f(float x) {
    float r; asm("ex2.approx.f32 %0, %1;" : "=f"(r) : "f"(x)); return r;
}
static __device__ __forceinline__ float lg2f(float x) {
    float r; asm("lg2.approx.f32 %0, %1;" : "=f"(r) : "f"(x)); return r;
}

__global__ __launch_bounds__(TPB, 2)
void dilate_kernel(const float* __restrict__ outputs,
                   const float* __restrict__ targets,
                   float* __restrict__ out) {
    const int b   = blockIdx.x;
    const int tid = threadIdx.x;
    const int w   = tid >> 5;
    const int l   = tid & 31;
    const int i   = 32 * w + l + 1;          // DP row (1-based)
    const bool row_ok = (i <= NN);

    __shared__ float o_s[8 * NN];            // [v][j], v<7; [7][j]=||o_j||^2
    __shared__ float bndA[NW][BNDW];         // fwd: R[32w][j] ; bwd: E[32w+33][j]
    __shared__ float bndB[NW][BNDW];         // bwd: s[32w+33][j]
    __shared__ float warpsum[NW];
    __shared__ float shape_s;

    const float* ob = outputs + (size_t)b * NN * NV;
    const float* tb = targets + (size_t)b * NN * NV;

    for (int k = tid; k < NN * NV; k += TPB) {
        int j = k / NV, v = k - j * NV;
        o_s[v * NN + j] = ob[k];
    }
    __syncthreads();
    for (int j = tid; j < NN; j += TPB) {
        float s = 0.f;
#pragma unroll
        for (int v = 0; v < NV; v++) { float x = o_s[v * NN + j]; s = fmaf(x, x, s); }
        o_s[7 * NN + j] = s;
    }
    float t[NV], tn = 0.f;
    if (row_ok) {
#pragma unroll
        for (int v = 0; v < NV; v++) { t[v] = tb[(i - 1) * NV + v]; tn = fmaf(t[v], t[v], tn); }
    }
    // forward boundary prefill: row 0 (all BIG except R[0][0]=0), column 0 for each band
    for (int k = tid; k < BNDW; k += TPB) bndA[0][k] = (k == 0) ? 0.f : BIG2;
    if (tid > 0 && tid < NW) bndA[tid][0] = BIG2;
    if (tid == 0) shape_s = 0.f;
    __syncthreads();

    float* gRb = g_R + (size_t)b * ND * DS;

    // ================= forward =================
    {
        float Rprev = BIG2, upc = BIG2, upp = BIG2, prevB = 0.f;
        const int off = 64 * w;
        const int pstart = off >> 5, pend = (off + 366) >> 5;
        for (int p = 0; p < 31; p++) {
            if (p >= pstart && p <= pend) {
                if (p == pstart && l == 0) prevB = bndA[w][0];
                int s = p << 5;
#pragma unroll 8
                for (int k = 0; k < 32; k++, s++) {
                    int j = s - off - l + 1;
                    bool act = row_ok && (j >= 1) && (j <= NN);
                    int jm = min(max(j - 1, 0), NN - 1);
                    float dot = 0.f;
#pragma unroll
                    for (int v = 0; v < NV; v++) dot = fmaf(t[v], o_s[v * NN + jm], dot);
                    float D2 = fmaxf(fmaf(-2.f, dot, tn + o_s[7 * NN + jm]), 0.f) * LOG2E;
                    float ru = upc, rd = upp, curB = 0.f;
                    if (l == 0) {
                        int jc = min(max(j, 0), BNDW - 1);
                        curB = bndA[w][jc];
                        ru = curB; rd = prevB;
                    }
                    float rl = Rprev;
                    float lo = fminf(rd, ru), hi = fmaxf(rd, ru);
                    float m  = fminf(lo, rl);
                    float md = fmaxf(lo, fminf(hi, rl));
                    float Mx = fmaxf(hi, rl);
                    float z  = 1.f + ex2f(m - md) + ex2f(m - Mx);
                    float Rn = D2 + m - lg2f(z);
                    Rn = act ? Rn : BIG2;
                    if (act) {
                        gRb[(size_t)(s - 32 * w + 2) * DS + i] = Rn;  // diag d = i+j
                        if (l == 31 && w < NW - 1) bndA[w + 1][j] = Rn;
                    }
                    float sh = __shfl_up_sync(FULLM, Rn, 1);
                    upp = upc; upc = sh;
                    if (l == 0) prevB = curB;
                    Rprev = Rn;
                }
            }
            __syncthreads();
        }
    }

    // re-init boundary arrays for backward (E=0, s=NEG beyond edges)
    for (int k = tid; k < NW * BNDW; k += TPB) {
        (&bndA[0][0])[k] = 0.f;
        (&bndB[0][0])[k] = NEGS;
    }
    __syncthreads();

    // ================= backward =================
    float acc = 0.f;
    {
        float Eprev = 0.f, Sprev = NEGS;     // (i, j+1)
        float Edn1  = 0.f, Sdn1  = NEGS;     // (i+1, j)
        float Edn2  = 0.f, Sdn2  = NEGS;     // (i+1, j+1)
        const int off = 64 * (10 - w);
        const int pstart = off >> 5, pend = (off + 366) >> 5;
        const int irow = min(i, DS - 1);
        float rring[PF];
        for (int p = 0; p < 32; p++) {
            if (p >= pstart && p <= pend) {
                int s0 = p << 5;
                if (p == pstart) {
#pragma unroll
                    for (int q = 0; q < PF; q++) {
                        int d = 1008 - 32 * w - (s0 + q);
                        d = min(max(d, 0), ND - 1);
                        rring[q] = gRb[(size_t)d * DS + irow];
                    }
                }
                int s = s0;
#pragma unroll 2
                for (int kb = 0; kb < 2; kb++) {
#pragma unroll
                    for (int kk = 0; kk < 16; kk++, s++) {
                        int j = 367 + off - s - l;
                        bool act = row_ok && (j >= 1) && (j <= NN);
                        float Rij = rring[kk];
                        {   // prefetch for step s+PF
                            int dpf = 1008 - 32 * w - (s + PF);
                            dpf = min(max(dpf, 0), ND - 1);
                            rring[kk] = gRb[(size_t)dpf * DS + irow];
                        }
                        if (l == 31) {       // cross-band successors from smem
                            int jc = min(max(j, 0), BNDW - 1);
                            Edn1 = bndA[w][jc];
                            Sdn1 = bndB[w][jc];
                        }
                        int jm = min(max(j - 1, 0), NN - 1);
                        float dot = 0.f;
#pragma unroll
                        for (int v = 0; v < NV; v++) dot = fmaf(t[v], o_s[v * NN + jm], dot);
                        float D2 = fmaxf(fmaf(-2.f, dot, tn + o_s[7 * NN + jm]), 0.f) * LOG2E;
                        float w1 = ex2f(Sdn1 - Rij);
                        float w2 = ex2f(Sprev - Rij);
                        float w3 = ex2f(Sdn2 - Rij);
                        float En = Edn1 * w1 + Eprev * w2 + Edn2 * w3;
                        if (i == NN && j == NN) { En = 1.f; shape_s = Rij * LN2; }
                        float Sn = Rij - D2;
                        En = act ? En : 0.f;
                        Sn = act ? Sn : NEGS;
                        if (act) {
                            float df = (float)(i - j);
                            acc = fmaf(En, df * df, acc);
                            if (l == 0 && w > 0) { bndA[w - 1][j] = En; bndB[w - 1][j] = Sn; }
                        }
                        float Es = __shfl_down_sync(FULLM, En, 1);
                        float Ss = __shfl_down_sync(FULLM, Sn, 1);
                        Edn2 = Edn1; Sdn2 = Sdn1;
                        Edn1 = Es;   Sdn1 = Ss;
                        Eprev = En;  Sprev = Sn;
                    }
                }
            }
            __syncthreads();
        }
    }

    // ------- reduce temporal accumulator, finalize in last CTA -------
#pragma unroll
    for (int o2 = 16; o2; o2 >>= 1) acc += __shfl_down_sync(FULLM, acc, o2);
    if (l == 0) warpsum[w] = acc;
    __syncthreads();
    if (tid == 0) {
        float sum = 0.f;
#pragma unroll
        for (int q = 0; q < NW; q++) sum += warpsum[q];
        atomicAdd(&g_temp_acc, (double)sum);
        atomicAdd(&g_shape_acc, (double)shape_s);
        __threadfence();
        unsigned old = atomicAdd(&g_done, 1u);
        if (old == NB - 1) {
            __threadfence();
            double shape    = g_shape_acc / (double)NB;
            double temporal = g_temp_acc / ((double)NN * NN * NB * NB);
            out[0] = (float)(0.5 * shape + 0.5 * temporal);
            g_shape_acc = 0.0;
            g_temp_acc  = 0.0;
            __threadfence();
            g_done = 0u;
        }
    }
}

extern "C" void kernel_launch(void* const* d_in, const int* in_sizes, int n_in,
                              void* d_out, int out_size) {
    const float* outputs = (const float*)d_in[0];
    const float* targets = (const float*)d_in[1];
    dilate_kernel<<<NB, TPB>>>(outputs, targets, (float*)d_out);
}